// round 15
// baseline (speedup 1.0000x reference)
#include <cuda_runtime.h>
#include <cuda_fp16.h>
#include <cstdint>

#define SEQ      4096
#define DM       768
#define NH       12
#define DH       64
#define QKV_COLS 2304
#define HSTRIDE  262144      // halves per head (4096*64)
#define EXP_SCALE 0.18033688011112042f   // log2(e)/8  (folded into Q)

// Scratch (no cudaMalloc allowed) — all fp16 fragment layouts
__device__ __half g_qfrag[NH * HSTRIDE];  // Q (pre-scaled by log2e/8), A16-frag
__device__ __half g_kfrag[NH * HSTRIDE];  // K: B16-frag (k=dim,n=key)
__device__ __half g_vfrag[NH * HSTRIDE];  // V: B16-frag (k=key,n=dim)
__device__ __half g_xa[SEQ * DM];         // x in A16-frag
__device__ __half g_w1r[DM * QKV_COLS];   // w_qkv in B16-frag
__device__ __half g_w2r[DM * DM];         // w_o in B16-frag
__device__ __half g_attn[SEQ * DM];       // attn out in A16-frag

// ---------------------------------------------------------------------------
// helpers
// ---------------------------------------------------------------------------
__device__ __forceinline__ uint32_t packh2(float lo, float hi) {
    __half2 h = __floats2half2_rn(lo, hi);
    return *reinterpret_cast<uint32_t*>(&h);
}
__device__ __forceinline__ uint32_t smem_u32(const void* p) {
    uint32_t a;
    asm("{ .reg .u64 t; cvta.to.shared.u64 t, %1; cvt.u32.u64 %0, t; }"
        : "=r"(a) : "l"(p));
    return a;
}
__device__ __forceinline__ void cp_async16(uint32_t s, const void* g) {
    asm volatile("cp.async.cg.shared.global [%0], [%1], 16;" :: "r"(s), "l"(g));
}
#define CP_COMMIT() asm volatile("cp.async.commit_group;" ::: "memory")
#define CP_WAIT0()  asm volatile("cp.async.wait_group 0;"  ::: "memory")

__device__ __forceinline__ void mma_f16(float c[4], const uint32_t a[4],
                                        uint32_t b0, uint32_t b1) {
    asm volatile(
        "mma.sync.aligned.m16n8k16.row.col.f32.f16.f16.f32 "
        "{%0,%1,%2,%3}, {%4,%5,%6,%7}, {%8,%9}, {%0,%1,%2,%3};"
        : "+f"(c[0]), "+f"(c[1]), "+f"(c[2]), "+f"(c[3])
        : "r"(a[0]), "r"(a[1]), "r"(a[2]), "r"(a[3]), "r"(b0), "r"(b1));
}
// fp16-accumulated variant (C-frag bit-identical to A-frag of P)
__device__ __forceinline__ void mma_f16h(uint32_t c[2], const uint32_t a[4],
                                         uint32_t b0, uint32_t b1) {
    asm volatile(
        "mma.sync.aligned.m16n8k16.row.col.f16.f16.f16.f16 "
        "{%0,%1}, {%2,%3,%4,%5}, {%6,%7}, {%0,%1};"
        : "+r"(c[0]), "+r"(c[1])
        : "r"(a[0]), "r"(a[1]), "r"(a[2]), "r"(a[3]), "r"(b0), "r"(b1));
}

// A16-frag block (16 rows x 16 cols, 256 halves): lane-contiguous uint4.
__host__ __device__ __forceinline__ int offA16(int rr, int cc) {
    return ((rr & 7) * 4 + ((cc & 7) >> 1)) * 8 + ((rr >> 3) + 2 * (cc >> 3)) * 2 + (cc & 1);
}
// B16-frag block (16 k x 8 n, 128 halves): lane-contiguous uint2.
__host__ __device__ __forceinline__ int offB16(int kk, int nn) {
    return (nn * 4 + ((kk & 7) >> 1)) * 4 + (kk >> 3) * 2 + (kk & 1);
}

// ---------------------------------------------------------------------------
// Merged preprocessing: fp32 -> fp16 fragment layouts for x, w_qkv, w_o
// ---------------------------------------------------------------------------
#define X4  (SEQ * DM / 4)
#define W14 (DM * QKV_COLS / 4)
#define W24 (DM * DM / 4)

__device__ __forceinline__ void a_frag_store(const float* __restrict__ s,
                                             __half* __restrict__ d,
                                             int i4, int K)
{
    int el = i4 * 4;
    int r = el / K, c = el % K;
    float4 v = ((const float4*)s)[i4];
    int KT = K >> 4;
    __half* base = d + (((size_t)(r >> 4) * KT + (c >> 4)) << 8);
    int rr = r & 15, cc = c & 15;
    *(uint32_t*)(base + offA16(rr, cc))     = packh2(v.x, v.y);
    *(uint32_t*)(base + offA16(rr, cc + 2)) = packh2(v.z, v.w);
}
__device__ __forceinline__ void b_frag_store(const float* __restrict__ s,
                                             __half* __restrict__ d,
                                             int i4, int K, int N)
{
    int el = i4 * 4;
    int r = el / N, c = el % N;
    float4 v = ((const float4*)s)[i4];
    float vv[4] = {v.x, v.y, v.z, v.w};
    int KT = K >> 4;
    __half* base = d + (((size_t)(c >> 3) * KT + (r >> 4)) << 7);
    int kk = r & 15, nn = c & 7;
#pragma unroll
    for (int i = 0; i < 4; i++)
        base[offB16(kk, nn + i)] = __float2half_rn(vv[i]);
}

__global__ void preproc_all(const float* __restrict__ x,
                            const float* __restrict__ w1,
                            const float* __restrict__ w2)
{
    int i4 = blockIdx.x * blockDim.x + threadIdx.x;
    if (i4 < X4) {
        a_frag_store(x, g_xa, i4, DM);
    } else if (i4 < X4 + W14) {
        b_frag_store(w1, g_w1r, i4 - X4, DM, QKV_COLS);
    } else if (i4 < X4 + W14 + W24) {
        b_frag_store(w2, g_w2r, i4 - X4 - W14, DM, DM);
    }
}

// ---------------------------------------------------------------------------
// fp16 GEMM (m16n8k16), fragment-layout operands, cp.async double-buffered.
// Template NT = B-tiles per warp: CTA tile = 128 x (32*NT).
// mode 0: C fp32 row-major + bias.  mode 1: bias + scatter fp16 Q/K/V frags.
// ---------------------------------------------------------------------------
#define GM_SMEM (4 * 4096 * 2)   // max instance (NT=4): 32768 B

template<int NT>
__global__ __launch_bounds__(256, 2) void tgemm_f16(
    const __half* __restrict__ A, const __half* __restrict__ B,
    const float* __restrict__ bias, float* __restrict__ C,
    int M, int N, int K, int mode)
{
    extern __shared__ __align__(16) __half smg[];
    __half* As = smg;                    // 2 x 4096 halves
    __half* Bs = smg + 8192;             // 2 x 1024*NT halves
    const uint32_t as_b = smem_u32(As);
    const uint32_t bs_b = smem_u32(Bs);

    const int tid  = threadIdx.x;
    const int wid  = tid >> 5;
    const int lane = tid & 31;
    const int g    = lane >> 2;
    const int t    = lane & 3;
    const int wm   = (wid & 1) * 64;
    const int wn   = (wid >> 1) * 8 * NT;
    const int amt  = (wid & 1) * 4;
    const int bnt  = (wid >> 1) * NT;
    const int row0 = blockIdx.y * 128;
    const int col0 = blockIdx.x * (32 * NT);
    const int mb0  = row0 >> 4;
    const int nb0  = col0 >> 3;
    const int KT   = K >> 4;

    float acc[4][NT][4];
#pragma unroll
    for (int mt = 0; mt < 4; mt++)
#pragma unroll
        for (int nt = 0; nt < NT; nt++)
#pragma unroll
            for (int j = 0; j < 4; j++) acc[mt][nt][j] = 0.f;

    const int niter = K >> 5;

    auto stage = [&](int it, int b) {
        const int kt0 = it * 2;
#pragma unroll
        for (int i = 0; i < 2; i++) {   // A: 512 uint4 chunks
            int idx = i * 256 + tid;
            int bl = idx >> 5, w = idx & 31;
            cp_async16(as_b + b * 8192 + bl * 512 + w * 16,
                       A + (((size_t)(mb0 + (bl >> 1)) * KT + kt0 + (bl & 1)) << 8) + w * 8);
        }
#pragma unroll
        for (int i = 0; i < NT / 2; i++) {  // B: 128*NT uint4 chunks
            int idx = i * 256 + tid;
            int bl2 = idx >> 4, w2 = idx & 15;
            cp_async16(bs_b + b * (2048 * NT) + bl2 * 256 + w2 * 16,
                       B + (((size_t)(nb0 + (bl2 >> 1)) * KT + kt0 + (bl2 & 1)) << 7) + w2 * 8);
        }
        CP_COMMIT();
    };

    stage(0, 0);
    CP_WAIT0();
    __syncthreads();

    for (int it = 0; it < niter; it++) {
        const int cb = it & 1;
        if (it + 1 < niter) stage(it + 1, cb ^ 1);

        const __half* Ac = As + cb * 4096;
        const __half* Bc = Bs + cb * (1024 * NT);
#pragma unroll
        for (int ks = 0; ks < 2; ks++) {
            uint32_t af[4][4];
#pragma unroll
            for (int mt = 0; mt < 4; mt++) {
                uint4 a4 = *(const uint4*)(Ac + ((amt + mt) * 2 + ks) * 256 + lane * 8);
                af[mt][0] = a4.x; af[mt][1] = a4.y; af[mt][2] = a4.z; af[mt][3] = a4.w;
            }
            uint32_t bf[NT][2];
#pragma unroll
            for (int nt = 0; nt < NT; nt++) {
                uint2 b2 = *(const uint2*)(Bc + ((bnt + nt) * 2 + ks) * 128 + lane * 4);
                bf[nt][0] = b2.x; bf[nt][1] = b2.y;
            }
#pragma unroll
            for (int mt = 0; mt < 4; mt++)
#pragma unroll
                for (int nt = 0; nt < NT; nt++)
                    mma_f16(acc[mt][nt], af[mt], bf[nt][0], bf[nt][1]);
        }
        if (it + 1 < niter) CP_WAIT0();
        __syncthreads();
    }

    if (mode == 0) {
#pragma unroll
        for (int mt = 0; mt < 4; mt++) {
            int r0 = row0 + wm + mt * 16 + g;
#pragma unroll
            for (int nt = 0; nt < NT; nt++) {
                int col = col0 + wn + nt * 8 + 2 * t;
                float2 bv = *(const float2*)&bias[col];
                *(float2*)&C[(size_t)r0 * N + col] =
                    make_float2(acc[mt][nt][0] + bv.x, acc[mt][nt][1] + bv.y);
                *(float2*)&C[(size_t)(r0 + 8) * N + col] =
                    make_float2(acc[mt][nt][2] + bv.x, acc[mt][nt][3] + bv.y);
            }
        }
    } else {
#pragma unroll
        for (int mt = 0; mt < 4; mt++) {
            int rb = row0 + wm + mt * 16 + g;     // rb&15 == g
#pragma unroll
            for (int nt = 0; nt < NT; nt++) {
                int colb = col0 + wn + nt * 8;
                int sec  = colb / 768;
                int cs   = colb % 768;
                int h    = cs >> 6;
                int dim0 = (cs & 63) + 2 * t;
                float2 bv = *(const float2*)&bias[colb + 2 * t];
                float v0 = acc[mt][nt][0] + bv.x, v1 = acc[mt][nt][1] + bv.y;
                float v2 = acc[mt][nt][2] + bv.x, v3 = acc[mt][nt][3] + bv.y;
                if (sec == 0) {
                    v0 *= EXP_SCALE; v1 *= EXP_SCALE;
                    v2 *= EXP_SCALE; v3 *= EXP_SCALE;
                    __half* base = g_qfrag + (size_t)h * HSTRIDE
                                 + (((size_t)(rb >> 4) * 4 + (dim0 >> 4)) << 8);
                    int cc = dim0 & 15;
                    *(uint32_t*)(base + offA16(g,     cc)) = packh2(v0, v1);
                    *(uint32_t*)(base + offA16(g + 8, cc)) = packh2(v2, v3);
                } else if (sec == 1) {
                    __half* base = g_kfrag + (size_t)h * HSTRIDE;
                    int ks = dim0 >> 4, kk = dim0 & 15;
                    int o1 = ((((rb >> 6) * 8 + ((rb & 63) >> 3)) * 4 + ks) << 7)
                             + offB16(kk, rb & 7);
                    *(uint32_t*)(base + o1) = packh2(v0, v1);
                    int rb2 = rb + 8;
                    int o2 = ((((rb2 >> 6) * 8 + ((rb2 & 63) >> 3)) * 4 + ks) << 7)
                             + offB16(kk, rb2 & 7);
                    *(uint32_t*)(base + o2) = packh2(v2, v3);
                } else {
                    __half* base = g_vfrag + (size_t)h * HSTRIDE;
                    int n = dim0 >> 3, nn = dim0 & 7;
                    int blk = ((((rb >> 6) * 4 + ((rb & 63) >> 4)) * 8 + n) << 7);
                    int kk = g;
                    base[blk + offB16(kk,     nn)]     = __float2half_rn(v0);
                    base[blk + offB16(kk,     nn + 1)] = __float2half_rn(v1);
                    base[blk + offB16(kk + 8, nn)]     = __float2half_rn(v2);
                    base[blk + offB16(kk + 8, nn + 1)] = __float2half_rn(v3);
                }
            }
        }
    }
}

// ---------------------------------------------------------------------------
// Flash attention, fp16 m16n8k16. S loop ks-outer/n-inner so consecutive
// HMMAs hit independent accumulators (8-wide chains). PV already kt-outer.
// S fp16-accum (C-frag == A-frag of P -> in-place h2exp2); PV fp32-accum.
// ---------------------------------------------------------------------------
#define AT_SMEM (4 * 4096 * 2)   // 32768 B

__global__ __launch_bounds__(128, 4) void attn_mma()
{
    extern __shared__ __align__(16) __half sm2[];
    __half* KsB = sm2;             // 2 x 4096 halves
    __half* VsB = sm2 + 8192;      // 2 x 4096 halves
    const uint32_t ks_b = smem_u32(KsB);
    const uint32_t vs_b = smem_u32(VsB);

    const int h    = blockIdx.y;
    const int qb   = blockIdx.x;   // 64-q tile
    const int tid  = threadIdx.x;
    const int wid  = tid >> 5;     // 0..3
    const int lane = tid & 31;
    const int g    = lane >> 2;
    const int t    = lane & 3;
    const int q0   = qb * 64;
    const int wrow = wid * 16;

    const __half* Kg = g_kfrag + (size_t)h * HSTRIDE;
    const __half* Vg = g_vfrag + (size_t)h * HSTRIDE;
    const __half* Qg = g_qfrag + (size_t)h * HSTRIDE;

    auto stage = [&](int kb, int b) {
#pragma unroll
        for (int i = 0; i < 4; i++) {
            int idx = i * 128 + tid;
            cp_async16(ks_b + b * 8192 + idx * 16, Kg + kb * 4096 + idx * 8);
            cp_async16(vs_b + b * 8192 + idx * 16, Vg + kb * 4096 + idx * 8);
        }
        CP_COMMIT();
    };

    stage(0, 0);

    // Q fragments straight from gmem (A16-frag, pre-scaled): 4 LDG.128
    const int qt = qb * 4 + wid;
    uint32_t qf[4][4];
#pragma unroll
    for (int ks = 0; ks < 4; ks++) {
        uint4 q4 = *(const uint4*)(Qg + (((size_t)qt * 4 + ks) << 8) + lane * 8);
        qf[ks][0] = q4.x; qf[ks][1] = q4.y; qf[ks][2] = q4.z; qf[ks][3] = q4.w;
    }

    CP_WAIT0();
    __syncthreads();

    float oacc[8][4];
#pragma unroll
    for (int n = 0; n < 8; n++)
#pragma unroll
        for (int j = 0; j < 4; j++) oacc[n][j] = 0.f;
    float lsum0 = 0.f, lsum1 = 0.f;

    const int NKB = SEQ / 64;
    for (int kb = 0; kb < NKB; kb++) {
        const int cb = kb & 1;
        if (kb + 1 < NKB) stage(kb + 1, cb ^ 1);

        const __half* Ks = KsB + cb * 4096;
        const __half* Vs = VsB + cb * 4096;

        // ---- S = Q @ K^T (fp16 accum): ks-outer => independent HMMA bursts --
        uint32_t sh[8][2];
#pragma unroll
        for (int n = 0; n < 8; n++) { sh[n][0] = 0u; sh[n][1] = 0u; }
#pragma unroll
        for (int ks = 0; ks < 4; ks++)
#pragma unroll
            for (int n = 0; n < 8; n++) {
                uint2 b2 = *(const uint2*)(Ks + (n * 4 + ks) * 128 + lane * 4);
                mma_f16h(sh[n], qf[ks], b2.x, b2.y);
            }

        // ---- softmax in place: P = 2^S (C-frag == A-frag), l via HADD2 ----
        uint32_t pa[4][4];
        __half2 lh0 = __floats2half2_rn(0.f, 0.f);
        __half2 lh1 = lh0;
#pragma unroll
        for (int kt = 0; kt < 4; kt++) {
            __half2 p0 = h2exp2(*(__half2*)&sh[2 * kt    ][0]);
            __half2 p1 = h2exp2(*(__half2*)&sh[2 * kt    ][1]);
            __half2 p2 = h2exp2(*(__half2*)&sh[2 * kt + 1][0]);
            __half2 p3 = h2exp2(*(__half2*)&sh[2 * kt + 1][1]);
            pa[kt][0] = *(uint32_t*)&p0;
            pa[kt][1] = *(uint32_t*)&p1;
            pa[kt][2] = *(uint32_t*)&p2;
            pa[kt][3] = *(uint32_t*)&p3;
            lh0 = __hadd2(lh0, __hadd2(p0, p2));
            lh1 = __hadd2(lh1, __hadd2(p1, p3));
        }
        float2 f0 = __half22float2(lh0);
        float2 f1 = __half22float2(lh1);
        lsum0 += f0.x + f0.y;
        lsum1 += f1.x + f1.y;

        // ---- O += P @ V (fp32 accum): kt-outer, n-inner (independent) ------
#pragma unroll
        for (int kt = 0; kt < 4; kt++)
#pragma unroll
            for (int n = 0; n < 8; n++) {
                uint2 v2 = *(const uint2*)(Vs + (kt * 8 + n) * 128 + lane * 4);
                mma_f16(oacc[n], pa[kt], v2.x, v2.y);
            }

        if (kb + 1 < NKB) CP_WAIT0();
        __syncthreads();
    }

    // cross-lane reduce over the 4 t-lanes
    lsum0 += __shfl_xor_sync(0xffffffffu, lsum0, 1);
    lsum0 += __shfl_xor_sync(0xffffffffu, lsum0, 2);
    lsum1 += __shfl_xor_sync(0xffffffffu, lsum1, 1);
    lsum1 += __shfl_xor_sync(0xffffffffu, lsum1, 2);

    // ---- epilogue: O / l -> g_attn (fp16 A16-frag for tgemm2) ---------------
    float inv0 = 1.f / lsum0;
    float inv1 = 1.f / lsum1;
    const int qto = (q0 + wrow) >> 4;   // == qb*4 + wid
#pragma unroll
    for (int n = 0; n < 8; n++) {
        int col = h * DH + n * 8 + 2 * t;
        __half* base = g_attn + (((size_t)qto * 48 + (col >> 4)) << 8);
        int cc = col & 15;
        *(uint32_t*)(base + offA16(g,     cc)) = packh2(oacc[n][0] * inv0, oacc[n][1] * inv0);
        *(uint32_t*)(base + offA16(g + 8, cc)) = packh2(oacc[n][2] * inv1, oacc[n][3] * inv1);
    }
}

// ---------------------------------------------------------------------------
extern "C" void kernel_launch(void* const* d_in, const int* in_sizes, int n_in,
                              void* d_out, int out_size)
{
    const float* x     = (const float*)d_in[0];
    const float* w_qkv = (const float*)d_in[1];
    const float* b_qkv = (const float*)d_in[2];
    const float* w_o   = (const float*)d_in[3];
    const float* b_o   = (const float*)d_in[4];
    float* out = (float*)d_out;

    __half* xa;   cudaGetSymbolAddress((void**)&xa,   g_xa);
    __half* w1r;  cudaGetSymbolAddress((void**)&w1r,  g_w1r);
    __half* w2r;  cudaGetSymbolAddress((void**)&w2r,  g_w2r);
    __half* attn; cudaGetSymbolAddress((void**)&attn, g_attn);

    cudaFuncSetAttribute(tgemm_f16<4>,
                         cudaFuncAttributeMaxDynamicSharedMemorySize, GM_SMEM);
    cudaFuncSetAttribute(tgemm_f16<2>,
                         cudaFuncAttributeMaxDynamicSharedMemorySize,
                         (2 * 4096 + 2 * 2048) * 2);
    cudaFuncSetAttribute(attn_mma,
                         cudaFuncAttributeMaxDynamicSharedMemorySize, AT_SMEM);

    // merged preprocessing: one launch covers x, w_qkv, w_o
    const int total4 = X4 + W14 + W24;
    preproc_all<<<(total4 + 255) / 256, 256>>>(x, w_qkv, w_o);

    dim3 blk(256);
    // QKV projection -> fp16 Q/K/V fragment arrays (NT=4, mode 1)
    tgemm_f16<4><<<dim3(QKV_COLS / 128, SEQ / 128), blk, GM_SMEM>>>(
        xa, w1r, b_qkv, nullptr, SEQ, QKV_COLS, DM, 1);

    // attention: 768 CTAs (64-q tiles), 128 threads
    attn_mma<<<dim3(SEQ / 64, NH), dim3(128), AT_SMEM>>>();

    // output projection (NT=2 -> 128x64 tiles, grid 384): fp32 row-major out
    tgemm_f16<2><<<dim3(DM / 64, SEQ / 128), blk, (2 * 4096 + 2 * 2048) * 2>>>(
        attn, w2r, b_o, out, SEQ, DM, DM, 0);
}

// round 16
// speedup vs baseline: 1.0070x; 1.0070x over previous
#include <cuda_runtime.h>
#include <cuda_fp16.h>
#include <cstdint>

#define SEQ      4096
#define DM       768
#define NH       12
#define DH       64
#define QKV_COLS 2304
#define HSTRIDE  262144      // halves per head (4096*64)
#define EXP_SCALE 0.18033688011112042f   // log2(e)/8  (folded into Q)

// Scratch (no cudaMalloc allowed) — all fp16 fragment layouts
__device__ __half g_qfrag[NH * HSTRIDE];  // Q (pre-scaled by log2e/8), A16-frag
__device__ __half g_kfrag[NH * HSTRIDE];  // K: B16-frag (k=dim,n=key)
__device__ __half g_vfrag[NH * HSTRIDE];  // V: B16-frag (k=key,n=dim)
__device__ __half g_xa[SEQ * DM];         // x in A16-frag
__device__ __half g_w1r[DM * QKV_COLS];   // w_qkv in B16-frag
__device__ __half g_w2r[DM * DM];         // w_o in B16-frag
__device__ __half g_attn[SEQ * DM];       // attn out in A16-frag

// ---------------------------------------------------------------------------
// helpers
// ---------------------------------------------------------------------------
__device__ __forceinline__ uint32_t packh2(float lo, float hi) {
    __half2 h = __floats2half2_rn(lo, hi);
    return *reinterpret_cast<uint32_t*>(&h);
}
__device__ __forceinline__ uint32_t smem_u32(const void* p) {
    uint32_t a;
    asm("{ .reg .u64 t; cvta.to.shared.u64 t, %1; cvt.u32.u64 %0, t; }"
        : "=r"(a) : "l"(p));
    return a;
}
__device__ __forceinline__ void cp_async16(uint32_t s, const void* g) {
    asm volatile("cp.async.cg.shared.global [%0], [%1], 16;" :: "r"(s), "l"(g));
}
#define CP_COMMIT() asm volatile("cp.async.commit_group;" ::: "memory")
#define CP_WAIT0()  asm volatile("cp.async.wait_group 0;"  ::: "memory")

__device__ __forceinline__ void mma_f16(float c[4], const uint32_t a[4],
                                        uint32_t b0, uint32_t b1) {
    asm volatile(
        "mma.sync.aligned.m16n8k16.row.col.f32.f16.f16.f32 "
        "{%0,%1,%2,%3}, {%4,%5,%6,%7}, {%8,%9}, {%0,%1,%2,%3};"
        : "+f"(c[0]), "+f"(c[1]), "+f"(c[2]), "+f"(c[3])
        : "r"(a[0]), "r"(a[1]), "r"(a[2]), "r"(a[3]), "r"(b0), "r"(b1));
}
// fp16-accumulated variant (C-frag bit-identical to A-frag of P)
__device__ __forceinline__ void mma_f16h(uint32_t c[2], const uint32_t a[4],
                                         uint32_t b0, uint32_t b1) {
    asm volatile(
        "mma.sync.aligned.m16n8k16.row.col.f16.f16.f16.f16 "
        "{%0,%1}, {%2,%3,%4,%5}, {%6,%7}, {%0,%1};"
        : "+r"(c[0]), "+r"(c[1])
        : "r"(a[0]), "r"(a[1]), "r"(a[2]), "r"(a[3]), "r"(b0), "r"(b1));
}

// A16-frag block (16 rows x 16 cols, 256 halves): lane-contiguous uint4.
__host__ __device__ __forceinline__ int offA16(int rr, int cc) {
    return ((rr & 7) * 4 + ((cc & 7) >> 1)) * 8 + ((rr >> 3) + 2 * (cc >> 3)) * 2 + (cc & 1);
}
// B16-frag block (16 k x 8 n, 128 halves): lane-contiguous uint2.
__host__ __device__ __forceinline__ int offB16(int kk, int nn) {
    return (nn * 4 + ((kk & 7) >> 1)) * 4 + (kk >> 3) * 2 + (kk & 1);
}

// ---------------------------------------------------------------------------
// Merged preprocessing: fp32 -> fp16 fragment layouts for x, w_qkv, w_o
// ---------------------------------------------------------------------------
#define X4  (SEQ * DM / 4)
#define W14 (DM * QKV_COLS / 4)
#define W24 (DM * DM / 4)

__device__ __forceinline__ void a_frag_store(const float* __restrict__ s,
                                             __half* __restrict__ d,
                                             int i4, int K)
{
    int el = i4 * 4;
    int r = el / K, c = el % K;
    float4 v = ((const float4*)s)[i4];
    int KT = K >> 4;
    __half* base = d + (((size_t)(r >> 4) * KT + (c >> 4)) << 8);
    int rr = r & 15, cc = c & 15;
    *(uint32_t*)(base + offA16(rr, cc))     = packh2(v.x, v.y);
    *(uint32_t*)(base + offA16(rr, cc + 2)) = packh2(v.z, v.w);
}
__device__ __forceinline__ void b_frag_store(const float* __restrict__ s,
                                             __half* __restrict__ d,
                                             int i4, int K, int N)
{
    int el = i4 * 4;
    int r = el / N, c = el % N;
    float4 v = ((const float4*)s)[i4];
    float vv[4] = {v.x, v.y, v.z, v.w};
    int KT = K >> 4;
    __half* base = d + (((size_t)(c >> 3) * KT + (r >> 4)) << 7);
    int kk = r & 15, nn = c & 7;
#pragma unroll
    for (int i = 0; i < 4; i++)
        base[offB16(kk, nn + i)] = __float2half_rn(vv[i]);
}

__global__ void preproc_all(const float* __restrict__ x,
                            const float* __restrict__ w1,
                            const float* __restrict__ w2)
{
    int i4 = blockIdx.x * blockDim.x + threadIdx.x;
    if (i4 < X4) {
        a_frag_store(x, g_xa, i4, DM);
    } else if (i4 < X4 + W14) {
        b_frag_store(w1, g_w1r, i4 - X4, DM, QKV_COLS);
    } else if (i4 < X4 + W14 + W24) {
        b_frag_store(w2, g_w2r, i4 - X4 - W14, DM, DM);
    }
}

// ---------------------------------------------------------------------------
// fp16 GEMM (m16n8k16), fragment-layout operands, cp.async double-buffered.
// 128x128x32 tile, 256 thr, 8 warps (known-good R14 config).
// mode 0: C fp32 row-major + bias.  mode 1: bias + scatter fp16 Q/K/V frags.
// ---------------------------------------------------------------------------
#define GM_SMEM (4 * 4096 * 2)   // 32768 B

__global__ __launch_bounds__(256, 2) void tgemm_f16(
    const __half* __restrict__ A, const __half* __restrict__ B,
    const float* __restrict__ bias, float* __restrict__ C,
    int M, int N, int K, int mode)
{
    extern __shared__ __align__(16) __half smg[];
    __half* As = smg;              // 2 x 4096 halves
    __half* Bs = smg + 8192;       // 2 x 4096 halves
    const uint32_t as_b = smem_u32(As);
    const uint32_t bs_b = smem_u32(Bs);

    const int tid  = threadIdx.x;
    const int wid  = tid >> 5;
    const int lane = tid & 31;
    const int g    = lane >> 2;
    const int t    = lane & 3;
    const int wm   = (wid & 1) * 64;
    const int wn   = (wid >> 1) * 32;
    const int amt  = (wid & 1) * 4;
    const int bnt  = (wid >> 1) * 4;
    const int row0 = blockIdx.y * 128;
    const int col0 = blockIdx.x * 128;
    const int mb0  = row0 >> 4;
    const int nb0  = col0 >> 3;
    const int KT   = K >> 4;

    float acc[4][4][4];
#pragma unroll
    for (int mt = 0; mt < 4; mt++)
#pragma unroll
        for (int nt = 0; nt < 4; nt++)
#pragma unroll
            for (int j = 0; j < 4; j++) acc[mt][nt][j] = 0.f;

    const int niter = K >> 5;

    auto stage = [&](int it, int b) {
        const int kt0 = it * 2;
#pragma unroll
        for (int i = 0; i < 2; i++) {
            int idx = i * 256 + tid;
            int bl = idx >> 5, w = idx & 31;
            cp_async16(as_b + b * 8192 + bl * 512 + w * 16,
                       A + (((size_t)(mb0 + (bl >> 1)) * KT + kt0 + (bl & 1)) << 8) + w * 8);
            int bl2 = idx >> 4, w2 = idx & 15;
            cp_async16(bs_b + b * 8192 + bl2 * 256 + w2 * 16,
                       B + (((size_t)(nb0 + (bl2 >> 1)) * KT + kt0 + (bl2 & 1)) << 7) + w2 * 8);
        }
        CP_COMMIT();
    };

    stage(0, 0);
    CP_WAIT0();
    __syncthreads();

    for (int it = 0; it < niter; it++) {
        const int cb = it & 1;
        if (it + 1 < niter) stage(it + 1, cb ^ 1);

        const __half* Ac = As + cb * 4096;
        const __half* Bc = Bs + cb * 4096;
#pragma unroll
        for (int ks = 0; ks < 2; ks++) {
            uint32_t af[4][4];
#pragma unroll
            for (int mt = 0; mt < 4; mt++) {
                uint4 a4 = *(const uint4*)(Ac + ((amt + mt) * 2 + ks) * 256 + lane * 8);
                af[mt][0] = a4.x; af[mt][1] = a4.y; af[mt][2] = a4.z; af[mt][3] = a4.w;
            }
            uint32_t bf[4][2];
#pragma unroll
            for (int nt = 0; nt < 4; nt++) {
                uint2 b2 = *(const uint2*)(Bc + ((bnt + nt) * 2 + ks) * 128 + lane * 4);
                bf[nt][0] = b2.x; bf[nt][1] = b2.y;
            }
#pragma unroll
            for (int mt = 0; mt < 4; mt++)
#pragma unroll
                for (int nt = 0; nt < 4; nt++)
                    mma_f16(acc[mt][nt], af[mt], bf[nt][0], bf[nt][1]);
        }
        if (it + 1 < niter) CP_WAIT0();
        __syncthreads();
    }

    if (mode == 0) {
#pragma unroll
        for (int mt = 0; mt < 4; mt++) {
            int r0 = row0 + wm + mt * 16 + g;
#pragma unroll
            for (int nt = 0; nt < 4; nt++) {
                int col = col0 + wn + nt * 8 + 2 * t;
                float2 bv = *(const float2*)&bias[col];
                *(float2*)&C[(size_t)r0 * N + col] =
                    make_float2(acc[mt][nt][0] + bv.x, acc[mt][nt][1] + bv.y);
                *(float2*)&C[(size_t)(r0 + 8) * N + col] =
                    make_float2(acc[mt][nt][2] + bv.x, acc[mt][nt][3] + bv.y);
            }
        }
    } else {
#pragma unroll
        for (int mt = 0; mt < 4; mt++) {
            int rb = row0 + wm + mt * 16 + g;     // rb&15 == g
#pragma unroll
            for (int nt = 0; nt < 4; nt++) {
                int colb = col0 + wn + nt * 8;
                int sec  = colb / 768;
                int cs   = colb % 768;
                int h    = cs >> 6;
                int dim0 = (cs & 63) + 2 * t;
                float2 bv = *(const float2*)&bias[colb + 2 * t];
                float v0 = acc[mt][nt][0] + bv.x, v1 = acc[mt][nt][1] + bv.y;
                float v2 = acc[mt][nt][2] + bv.x, v3 = acc[mt][nt][3] + bv.y;
                if (sec == 0) {
                    v0 *= EXP_SCALE; v1 *= EXP_SCALE;
                    v2 *= EXP_SCALE; v3 *= EXP_SCALE;
                    __half* base = g_qfrag + (size_t)h * HSTRIDE
                                 + (((size_t)(rb >> 4) * 4 + (dim0 >> 4)) << 8);
                    int cc = dim0 & 15;
                    *(uint32_t*)(base + offA16(g,     cc)) = packh2(v0, v1);
                    *(uint32_t*)(base + offA16(g + 8, cc)) = packh2(v2, v3);
                } else if (sec == 1) {
                    __half* base = g_kfrag + (size_t)h * HSTRIDE;
                    int ks = dim0 >> 4, kk = dim0 & 15;
                    int o1 = ((((rb >> 6) * 8 + ((rb & 63) >> 3)) * 4 + ks) << 7)
                             + offB16(kk, rb & 7);
                    *(uint32_t*)(base + o1) = packh2(v0, v1);
                    int rb2 = rb + 8;
                    int o2 = ((((rb2 >> 6) * 8 + ((rb2 & 63) >> 3)) * 4 + ks) << 7)
                             + offB16(kk, rb2 & 7);
                    *(uint32_t*)(base + o2) = packh2(v2, v3);
                } else {
                    __half* base = g_vfrag + (size_t)h * HSTRIDE;
                    int n = dim0 >> 3, nn = dim0 & 7;
                    int blk = ((((rb >> 6) * 4 + ((rb & 63) >> 4)) * 8 + n) << 7);
                    int kk = g;
                    base[blk + offB16(kk,     nn)]     = __float2half_rn(v0);
                    base[blk + offB16(kk,     nn + 1)] = __float2half_rn(v1);
                    base[blk + offB16(kk + 8, nn)]     = __float2half_rn(v2);
                    base[blk + offB16(kk + 8, nn + 1)] = __float2half_rn(v3);
                }
            }
        }
    }
}

// ---------------------------------------------------------------------------
// Flash attention, fp16 m16n8k16. K-tile widened to 128 keys (16 iterations):
// halves barrier/loop overhead, doubles MMA batch depth per phase.
// S fp16-accum, ks-outer (independent chains); PV fp32-accum, kt-outer.
// smem 64KB -> 3 CTAs/SM.
// ---------------------------------------------------------------------------
#define AT_SMEM (4 * 8192 * 2)   // 65536 B

__global__ __launch_bounds__(128, 3) void attn_mma()
{
    extern __shared__ __align__(16) __half sm2[];
    __half* KsB = sm2;              // 2 x 8192 halves
    __half* VsB = sm2 + 16384;      // 2 x 8192 halves
    const uint32_t ks_b = smem_u32(KsB);
    const uint32_t vs_b = smem_u32(VsB);

    const int h    = blockIdx.y;
    const int qb   = blockIdx.x;   // 64-q tile
    const int tid  = threadIdx.x;
    const int wid  = tid >> 5;     // 0..3
    const int lane = tid & 31;
    const int g    = lane >> 2;
    const int t    = lane & 3;
    const int q0   = qb * 64;
    const int wrow = wid * 16;

    const __half* Kg = g_kfrag + (size_t)h * HSTRIDE;
    const __half* Vg = g_vfrag + (size_t)h * HSTRIDE;
    const __half* Qg = g_qfrag + (size_t)h * HSTRIDE;

    // stage 128 keys (two 64-key blocks) into buffer b
    auto stage = [&](int kb2, int b) {
#pragma unroll
        for (int i = 0; i < 8; i++) {
            int idx = i * 128 + tid;   // 1024 chunks of 16B per 128-key tile
            cp_async16(ks_b + b * 16384 + idx * 16, Kg + kb2 * 8192 + idx * 8);
            cp_async16(vs_b + b * 16384 + idx * 16, Vg + kb2 * 8192 + idx * 8);
        }
        CP_COMMIT();
    };

    stage(0, 0);

    // Q fragments straight from gmem (A16-frag, pre-scaled): 4 LDG.128
    const int qt = qb * 4 + wid;
    uint32_t qf[4][4];
#pragma unroll
    for (int ks = 0; ks < 4; ks++) {
        uint4 q4 = *(const uint4*)(Qg + (((size_t)qt * 4 + ks) << 8) + lane * 8);
        qf[ks][0] = q4.x; qf[ks][1] = q4.y; qf[ks][2] = q4.z; qf[ks][3] = q4.w;
    }

    CP_WAIT0();
    __syncthreads();

    float oacc[8][4];
#pragma unroll
    for (int n = 0; n < 8; n++)
#pragma unroll
        for (int j = 0; j < 4; j++) oacc[n][j] = 0.f;
    float lsum0 = 0.f, lsum1 = 0.f;

    const int NKB2 = SEQ / 128;   // 32 half-iterations -> 16 wide iterations
    for (int kb2 = 0; kb2 < NKB2; kb2++) {
        const int cb = kb2 & 1;
        if (kb2 + 1 < NKB2) stage(kb2 + 1, cb ^ 1);

        const __half* Ks = KsB + cb * 8192;
        const __half* Vs = VsB + cb * 8192;

        __half2 lh0 = __floats2half2_rn(0.f, 0.f);
        __half2 lh1 = lh0;

        // process the two 64-key halves of the wide tile
#pragma unroll
        for (int half = 0; half < 2; half++) {
            const __half* Kh = Ks + half * 4096;
            const __half* Vh = Vs + half * 4096;

            // ---- S = Q @ K^T (fp16 accum): ks-outer, 8 indep chains --------
            uint32_t sh[8][2];
#pragma unroll
            for (int n = 0; n < 8; n++) { sh[n][0] = 0u; sh[n][1] = 0u; }
#pragma unroll
            for (int ks = 0; ks < 4; ks++)
#pragma unroll
                for (int n = 0; n < 8; n++) {
                    uint2 b2 = *(const uint2*)(Kh + (n * 4 + ks) * 128 + lane * 4);
                    mma_f16h(sh[n], qf[ks], b2.x, b2.y);
                }

            // ---- softmax in place: P = 2^S, l via HADD2 --------------------
            uint32_t pa[4][4];
#pragma unroll
            for (int kt = 0; kt < 4; kt++) {
                __half2 p0 = h2exp2(*(__half2*)&sh[2 * kt    ][0]);
                __half2 p1 = h2exp2(*(__half2*)&sh[2 * kt    ][1]);
                __half2 p2 = h2exp2(*(__half2*)&sh[2 * kt + 1][0]);
                __half2 p3 = h2exp2(*(__half2*)&sh[2 * kt + 1][1]);
                pa[kt][0] = *(uint32_t*)&p0;
                pa[kt][1] = *(uint32_t*)&p1;
                pa[kt][2] = *(uint32_t*)&p2;
                pa[kt][3] = *(uint32_t*)&p3;
                lh0 = __hadd2(lh0, __hadd2(p0, p2));
                lh1 = __hadd2(lh1, __hadd2(p1, p3));
            }

            // ---- O += P @ V (fp32 accum): kt-outer, n-inner ----------------
#pragma unroll
            for (int kt = 0; kt < 4; kt++)
#pragma unroll
                for (int n = 0; n < 8; n++) {
                    uint2 v2 = *(const uint2*)(Vh + (kt * 8 + n) * 128 + lane * 4);
                    mma_f16(oacc[n], pa[kt], v2.x, v2.y);
                }
        }

        float2 f0 = __half22float2(lh0);
        float2 f1 = __half22float2(lh1);
        lsum0 += f0.x + f0.y;
        lsum1 += f1.x + f1.y;

        if (kb2 + 1 < NKB2) CP_WAIT0();
        __syncthreads();
    }

    // cross-lane reduce over the 4 t-lanes
    lsum0 += __shfl_xor_sync(0xffffffffu, lsum0, 1);
    lsum0 += __shfl_xor_sync(0xffffffffu, lsum0, 2);
    lsum1 += __shfl_xor_sync(0xffffffffu, lsum1, 1);
    lsum1 += __shfl_xor_sync(0xffffffffu, lsum1, 2);

    // ---- epilogue: O / l -> g_attn (fp16 A16-frag for tgemm2) ---------------
    float inv0 = 1.f / lsum0;
    float inv1 = 1.f / lsum1;
    const int qto = (q0 + wrow) >> 4;   // == qb*4 + wid
#pragma unroll
    for (int n = 0; n < 8; n++) {
        int col = h * DH + n * 8 + 2 * t;
        __half* base = g_attn + (((size_t)qto * 48 + (col >> 4)) << 8);
        int cc = col & 15;
        *(uint32_t*)(base + offA16(g,     cc)) = packh2(oacc[n][0] * inv0, oacc[n][1] * inv0);
        *(uint32_t*)(base + offA16(g + 8, cc)) = packh2(oacc[n][2] * inv1, oacc[n][3] * inv1);
    }
}

// ---------------------------------------------------------------------------
extern "C" void kernel_launch(void* const* d_in, const int* in_sizes, int n_in,
                              void* d_out, int out_size)
{
    const float* x     = (const float*)d_in[0];
    const float* w_qkv = (const float*)d_in[1];
    const float* b_qkv = (const float*)d_in[2];
    const float* w_o   = (const float*)d_in[3];
    const float* b_o   = (const float*)d_in[4];
    float* out = (float*)d_out;

    __half* xa;   cudaGetSymbolAddress((void**)&xa,   g_xa);
    __half* w1r;  cudaGetSymbolAddress((void**)&w1r,  g_w1r);
    __half* w2r;  cudaGetSymbolAddress((void**)&w2r,  g_w2r);
    __half* attn; cudaGetSymbolAddress((void**)&attn, g_attn);

    cudaFuncSetAttribute(tgemm_f16,
                         cudaFuncAttributeMaxDynamicSharedMemorySize, GM_SMEM);
    cudaFuncSetAttribute(attn_mma,
                         cudaFuncAttributeMaxDynamicSharedMemorySize, AT_SMEM);

    // merged preprocessing: one launch covers x, w_qkv, w_o
    const int total4 = X4 + W14 + W24;
    preproc_all<<<(total4 + 255) / 256, 256>>>(x, w_qkv, w_o);

    dim3 blk(256);
    // QKV projection -> fp16 Q/K/V fragment arrays (mode 1, Q pre-scaled)
    tgemm_f16<<<dim3(QKV_COLS / 128, SEQ / 128), blk, GM_SMEM>>>(
        xa, w1r, b_qkv, nullptr, SEQ, QKV_COLS, DM, 1);

    // attention: 768 CTAs (64-q tiles), 128 threads, 128-key wide iterations
    attn_mma<<<dim3(SEQ / 64, NH), dim3(128), AT_SMEM>>>();

    // output projection (128x128 tiles, known-good): fp32 row-major out
    tgemm_f16<<<dim3(DM / 128, SEQ / 128), blk, GM_SMEM>>>(
        attn, w2r, b_o, out, SEQ, DM, DM, 0);
}